// round 5
// baseline (speedup 1.0000x reference)
#include <cuda_runtime.h>
#include <cuda_bf16.h>

// FrequencyFilter: gather 256 ch -> K-tap gauss_low (sigma=2000 samp) low-pass
// -> filt = x - low + mean(low) -> K-tap gauss_high (sigma=100 samp) smoothing.
// K = 12001 (arange fp quirk), pad = (K-1)//2 = 6000. Parameterized at runtime.
//
// Strategy: both Gaussians are heavily bandlimited.
//  * low computed at stride-64 nodes from 4-sample presums (S4) with aggregated
//    4-tap weights, cubic-Lagrange interpolated.
//  * output computed at stride-8 nodes (polyphase correlation, ~1400 effective
//    taps of gauss_high), cubic-Lagrange interpolated to full resolution.
//  * mean(low) via prefix sums of gauss_low + channel-summed S4.

#define T_LEN   100000
#define C_SEL   256
#define C_IN    512

// ---- low-pass stage ----
#define S4_N     25000            // 4-sample presum blocks
#define S4_PADL  1520
#define S4_PADR  1664
#define S4_ROWS  (S4_PADL + S4_N + S4_PADR)   // 28184
#define WA_PAD   128
#define WA_SIZE  3456             // padded aggregated low kernel (3001 valid)
#define NLN      1568             // low nodes, node j at t = 64*(j-1)

// ---- filt buffer (zero padded in time) ----
#define F_PADL   640
#define F_PADR   736
#define F_ROWS   (F_PADL + T_LEN + F_PADR)    // 101376

// ---- high-pass output nodes ----
#define NYN      12512            // node i at t = 8*i - 8 (12503 used + slack)

// ------------------- device scratch (static, no allocation) -------------------
__device__ __align__(16) float g_P[12002];                 // prefix of gauss_low
__device__ __align__(16) float g_WA[WA_SIZE];              // aggregated low kernel /4, zero padded
__device__ float g_mean_num;                               // numerator of mean(low)
__device__ __align__(16) float g_S4[(size_t)S4_ROWS * 256];          // 28.9 MB
__device__ __align__(16) float g_LNp[4 * NLN * 256];                 // phase-partial low nodes
__device__ __align__(16) float g_LN[NLN * 256];                      // low nodes
__device__ __align__(16) float g_FILT[(size_t)F_ROWS * 256];         // 103.8 MB
__device__ __align__(16) float g_YN[(size_t)NYN * 256];              // 12.8 MB

// ------------------- K2: prefix of gauss_low + aggregated kernel + init -------------------
__global__ void k2_prep(const float* __restrict__ gl, int K, int pad) {
    __shared__ float tot[256];
    const int tid = threadIdx.x;
    const int base = tid * 48;
    float s = 0.f;
    for (int i = 0; i < 48; i++) { int k = base + i; if (k < K) s += gl[k]; }
    tot[tid] = s;
    __syncthreads();
    if (tid == 0) {
        float run = 0.f;
        for (int i = 0; i < 256; i++) { float v = tot[i]; tot[i] = run; run += v; }
        g_P[K] = run;
        g_mean_num = 0.f;
    }
    __syncthreads();
    float run = tot[tid];
    for (int i = 0; i < 48; i++) {
        int k = base + i;
        if (k < K) { g_P[k] = run; run += gl[k]; }
    }
    __syncthreads();
    // aggregated 4-tap low kernel (averaged weight); block QQ holds taps
    // k = 4*(QQ-1500) + pad + {0..3}, zero outside QQ in [0,3000]
    for (int q = tid; q < WA_SIZE; q += 256) {
        int QQ = q - WA_PAD;
        float v = 0.f;
        if (QQ >= 0 && QQ <= 3000) {
            int lo = 4 * QQ - 6000 + pad;
            int hi = min(lo + 4, K);
            lo = max(lo, 0);
            if (hi > lo) v = 0.25f * (g_P[hi] - g_P[lo]);
        }
        g_WA[q] = v;
    }
}

// ------------------- K3: 4-sample presums (zero-padded rows) -------------------
__global__ void k3_presum(const float* __restrict__ x, const int* __restrict__ sel) {
    const int nb = blockIdx.x;               // [0, S4_ROWS)
    const int c = threadIdx.x;
    const int n = nb - S4_PADL;
    float v = 0.f;
    if (n >= 0 && n < S4_N) {
        const int ci = __ldg(&sel[c]);
        const float* xp = x + (size_t)(4 * n) * C_IN + ci;
        v = (xp[0] + xp[C_IN]) + (xp[2 * C_IN] + xp[3 * C_IN]);
    }
    g_S4[(size_t)nb * 256 + c] = v;
}

// ------------------- K3b: mean(low) numerator -------------------
__global__ void k3b_mean(int K, int pad) {
    const int n = blockIdx.x * 256 + threadIdx.x;
    float part = 0.f;
    if (n < S4_N) {
        const float4* row = (const float4*)(g_S4 + (size_t)(n + S4_PADL) * 256);
        float s = 0.f;
        #pragma unroll 8
        for (int i = 0; i < 64; i++) { float4 v = row[i]; s += (v.x + v.y) + (v.z + v.w); }
        float cf = 0.f;
        #pragma unroll
        for (int i = 0; i < 4; i++) {
            int m = 4 * n + i;
            cf += g_P[min(m + pad + 1, K)] - g_P[max(0, m + pad + 1 - T_LEN)];
        }
        part = s * cf * 0.25f;
    }
    #pragma unroll
    for (int o = 16; o > 0; o >>= 1) part += __shfl_down_sync(0xffffffffu, part, o);
    __shared__ float sw[8];
    if ((threadIdx.x & 31) == 0) sw[threadIdx.x >> 5] = part;
    __syncthreads();
    if (threadIdx.x == 0) {
        float s = 0.f;
        #pragma unroll
        for (int i = 0; i < 8; i++) s += sw[i];
        atomicAdd(&g_mean_num, s);
    }
}

// ------------------- K4: low-pass node values (16-phase, split over 4 blocks) -------------------
__global__ void __launch_bounds__(256) k4_lownodes() {
    const int warp = threadIdx.x >> 5, lane = threadIdx.x & 31;
    const int grp = blockIdx.x * 2 + (warp >> 2);   // node group [0,196)
    const int cp  = (warp & 3) * 32 + lane;         // float2 channel index [0,128)
    const int rq  = blockIdx.y;                     // phase quarter [0,4)
    const int j0  = grp * 8;

    float2 acc[8];
    #pragma unroll
    for (int i = 0; i < 8; i++) acc[i] = make_float2(0.f, 0.f);

    const float2* S42 = (const float2*)g_S4;

    for (int rr = 0; rr < 4; rr++) {
        const int r = rq * 4 + rr;
        const int roff = r - 1500 + 16 * (j0 - 1) + S4_PADL;  // buffer row at v=0
        float wprev[7];
        #pragma unroll
        for (int t = 0; t < 7; t++) wprev[t] = 0.f;           // W(e<0) = 0 (padding)
        for (int vb = 0; vb < 200; vb += 8) {
            float w8[8];
            #pragma unroll
            for (int u = 0; u < 8; u++) w8[u] = g_WA[WA_PAD + 16 * (vb + u) + r];
            #pragma unroll
            for (int u = 0; u < 8; u++) {
                float2 sv = S42[(size_t)(16 * (vb + u) + roff) * 128 + cp];
                #pragma unroll
                for (int ii = 0; ii < 8; ii++) {
                    int e = u - ii;
                    float w = (e >= 0) ? w8[e] : wprev[7 + e];
                    acc[ii].x += sv.x * w;
                    acc[ii].y += sv.y * w;
                }
            }
            #pragma unroll
            for (int t = 0; t < 7; t++) wprev[t] = w8[t + 1];
        }
    }
    float2* out = (float2*)(g_LNp + (size_t)rq * NLN * 256);
    #pragma unroll
    for (int ii = 0; ii < 8; ii++)
        out[(size_t)(j0 + ii) * 128 + cp] = acc[ii];
}

// ------------------- K4c: combine phase partials -------------------
__global__ void k4c_combine() {
    const size_t i = (size_t)blockIdx.x * 256 + threadIdx.x;   // NLN*256
    const size_t S = (size_t)NLN * 256;
    g_LN[i] = (g_LNp[i] + g_LNp[S + i]) + (g_LNp[2 * S + i] + g_LNp[3 * S + i]);
}

// ------------------- K5: materialize filt = x - interp(low) + mean (zero padded) -------------------
__global__ void k5_filt(const float* __restrict__ x, const int* __restrict__ sel) {
    const int row = blockIdx.x;            // [0, F_ROWS)
    const int m = row - F_PADL;
    const int c = threadIdx.x;
    float v = 0.f;
    if (m >= 0 && m < T_LEN) {
        const int j0 = m >> 6;
        const float s = (float)(m & 63) * (1.f / 64.f);
        const float sm1 = s + 1.f, s1 = s - 1.f, s2 = s - 2.f;
        const float wm1 = -s * s1 * s2 * (1.f / 6.f);
        const float w0  = sm1 * s1 * s2 * 0.5f;
        const float w1  = -sm1 * s * s2 * 0.5f;
        const float w2  = sm1 * s * s1 * (1.f / 6.f);
        const float* ln = g_LN + (size_t)j0 * 256 + c;
        const float lowI = wm1 * ln[0] + w0 * ln[256] + w1 * ln[512] + w2 * ln[768];
        const float mean = g_mean_num * (1.f / 25600000.f);
        v = x[(size_t)m * C_IN + __ldg(&sel[c])] - lowI + mean;
    }
    g_FILT[(size_t)row * 256 + c] = v;
}

// ------------------- K6: high-pass conv at stride-8 output nodes (8-phase) -------------------
// Node i at t = 8i - 8. Y[i] = sum_k wh[k] * filt[t + k - pad].
// k = 8*(c) + rr + (pad + 8) for c = cb+u-ii.
__global__ void __launch_bounds__(256) k6_conv(const float* __restrict__ wh, int wc) {
    const int warp = threadIdx.x >> 5, lane = threadIdx.x & 31;
    const int grp = blockIdx.x * 2 + (warp >> 2);   // node group [0,1564)
    const int cp  = (warp & 3) * 32 + lane;         // float2 channel index [0,128)
    const int i0  = grp * 8;

    float2 acc[8];
    #pragma unroll
    for (int i = 0; i < 8; i++) acc[i] = make_float2(0.f, 0.f);

    const float2* F2 = (const float2*)g_FILT;

    for (int rr = 0; rr < 8; rr++) {
        float wprev[7];
        #pragma unroll
        for (int t = 0; t < 7; t++) wprev[t] = __ldg(&wh[wc + 8 * (-87 + t) + rr]);
        for (int cb = -80; cb <= 80; cb += 8) {
            float w8[8];
            #pragma unroll
            for (int u = 0; u < 8; u++) w8[u] = __ldg(&wh[wc + 8 * (cb + u) + rr]);
            #pragma unroll
            for (int u = 0; u < 8; u++) {
                const int m = 8 * (i0 + cb + u) + rr;   // filt time index
                float2 fv = F2[(size_t)(m + F_PADL) * 128 + cp];
                #pragma unroll
                for (int ii = 0; ii < 8; ii++) {
                    int e = u - ii;
                    float w = (e >= 0) ? w8[e] : wprev[7 + e];
                    acc[ii].x += fv.x * w;
                    acc[ii].y += fv.y * w;
                }
            }
            #pragma unroll
            for (int t = 0; t < 7; t++) wprev[t] = w8[t + 1];
        }
    }
    float2* Y2 = (float2*)g_YN;
    #pragma unroll
    for (int ii = 0; ii < 8; ii++)
        Y2[(size_t)(i0 + ii) * 128 + cp] = acc[ii];
}

// ------------------- K7: cubic interpolation to full-resolution output -------------------
__global__ void k7_out(float* __restrict__ out) {
    const int t  = blockIdx.x * 4 + (threadIdx.x >> 6);
    const int cq = threadIdx.x & 63;
    const int i0 = t >> 3;
    const float s = (float)(t & 7) * 0.125f;
    const float sm1 = s + 1.f, s1 = s - 1.f, s2 = s - 2.f;
    const float wm1 = -s * s1 * s2 * (1.f / 6.f);
    const float w0  = sm1 * s1 * s2 * 0.5f;
    const float w1  = -sm1 * s * s2 * 0.5f;
    const float w2  = sm1 * s * s1 * (1.f / 6.f);
    const float4* Y = (const float4*)g_YN + (size_t)i0 * 64 + cq;
    float4 a = Y[0], b = Y[64], c4 = Y[128], d = Y[192];
    float4 r;
    r.x = wm1 * a.x + w0 * b.x + w1 * c4.x + w2 * d.x;
    r.y = wm1 * a.y + w0 * b.y + w1 * c4.y + w2 * d.y;
    r.z = wm1 * a.z + w0 * b.z + w1 * c4.z + w2 * d.z;
    r.w = wm1 * a.w + w0 * b.w + w1 * c4.w + w2 * d.w;
    ((float4*)out)[(size_t)t * 64 + cq] = r;
}

// ------------------- launch -------------------
extern "C" void kernel_launch(void* const* d_in, const int* in_sizes, int n_in,
                              void* d_out, int out_size) {
    const float* x   = (const float*)d_in[0];   // firings (1,100000,512)
    const float* gl  = (const float*)d_in[1];   // gauss_low (K taps)
    const float* gh  = (const float*)d_in[2];   // gauss_high (K taps)
    const int*   sel = (const int*)d_in[3];     // sel_idx (256)
    float* out = (float*)d_out;

    const int K   = in_sizes[1];                // 12001 (arange fp), robust to 12000
    const int pad = (K - 1) / 2;                // TF SAME left pad

    (void)n_in; (void)out_size;

    k2_prep<<<1, 256>>>(gl, K, pad);
    k3_presum<<<S4_ROWS, 256>>>(x, sel);
    k3b_mean<<<98, 256>>>(K, pad);
    k4_lownodes<<<dim3(98, 4), 256>>>();
    k4c_combine<<<NLN, 256>>>();
    k5_filt<<<F_ROWS, 256>>>(x, sel);
    k6_conv<<<782, 256>>>(gh, pad + 8);
    k7_out<<<25000, 256>>>(out);
}

// round 6
// speedup vs baseline: 1.4338x; 1.4338x over previous
#include <cuda_runtime.h>
#include <cuda_bf16.h>

// FrequencyFilter: gather 256 ch -> K-tap gauss_low (sigma=2000 samp) low-pass
// -> filt = x - low + mean(low) -> K-tap gauss_high (sigma=100 samp) smoothing.
// K = 12001, pad = (K-1)//2 = 6000 (parameterized at runtime).
//
// Strategy: both Gaussians are heavily bandlimited.
//  * low computed at stride-64 nodes from 4-sample presums (S4) with aggregated
//    4-tap weights (16-phase polyphase, phase-per-block), cubic interpolated.
//  * output computed at stride-8 nodes (8-phase polyphase over ~±5 sigma of
//    gauss_high, phases split over 2 blocks), cubic interpolated to full res.
//  * mean(low) via prefix sums of gauss_low + channel-summed S4.

#define T_LEN   100000
#define C_SEL   256
#define C_IN    512

// ---- low-pass stage ----
#define S4_N     25000            // 4-sample presum blocks
#define S4_PADL  1520
#define S4_PADR  1664
#define S4_ROWS  (S4_PADL + S4_N + S4_PADR)   // 28184
#define WA_PAD   128
#define WA_SIZE  3456             // padded aggregated low kernel (3001 valid)
#define NLN      1568             // low nodes, node j at t = 64*(j-1)
#define NPHASE   16

// ---- filt buffer (zero padded in time) ----
#define F_PADL   640
#define F_PADR   736
#define F_ROWS   (F_PADL + T_LEN + F_PADR)    // 101376

// ---- high-pass output nodes ----
#define NYN      12512            // node i at t = 8*i - 8 (12503 used + slack)

// ------------------- device scratch (static, no allocation) -------------------
__device__ __align__(16) float g_P[12002];                 // prefix of gauss_low
__device__ __align__(16) float g_WA[WA_SIZE];              // aggregated low kernel /4
__device__ float g_mean_num;                               // numerator of mean(low)
__device__ __align__(16) float g_S4[(size_t)S4_ROWS * 256];            // 28.9 MB
__device__ __align__(16) float g_LNp[(size_t)NPHASE * NLN * 256];      // 25.7 MB
__device__ __align__(16) float g_LN[NLN * 256];                        // 1.6 MB
__device__ __align__(16) float g_FILT[(size_t)F_ROWS * 256];           // 103.8 MB
__device__ __align__(16) float g_YNp[(size_t)2 * NYN * 256];           // 25.6 MB

// ------------------- K2: prefix of gauss_low + aggregated kernel + init -------------------
__global__ void k2_prep(const float* __restrict__ gl, int K, int pad) {
    __shared__ float tot[256];
    const int tid = threadIdx.x;
    const int base = tid * 48;
    float s = 0.f;
    for (int i = 0; i < 48; i++) { int k = base + i; if (k < K) s += gl[k]; }
    tot[tid] = s;
    __syncthreads();
    if (tid == 0) {
        float run = 0.f;
        for (int i = 0; i < 256; i++) { float v = tot[i]; tot[i] = run; run += v; }
        g_P[K] = run;
        g_mean_num = 0.f;
    }
    __syncthreads();
    float run = tot[tid];
    for (int i = 0; i < 48; i++) {
        int k = base + i;
        if (k < K) { g_P[k] = run; run += gl[k]; }
    }
    __syncthreads();
    // aggregated 4-tap low kernel (averaged weight); block QQ holds taps
    // k = 4*(QQ-1500) + pad + {0..3}, zero outside QQ in [0,3000]
    for (int q = tid; q < WA_SIZE; q += 256) {
        int QQ = q - WA_PAD;
        float v = 0.f;
        if (QQ >= 0 && QQ <= 3000) {
            int lo = 4 * QQ - 6000 + pad;
            int hi = min(lo + 4, K);
            lo = max(lo, 0);
            if (hi > lo) v = 0.25f * (g_P[hi] - g_P[lo]);
        }
        g_WA[q] = v;
    }
}

// ------------------- K3: 4-sample presums (zero-padded rows) -------------------
__global__ void k3_presum(const float* __restrict__ x, const int* __restrict__ sel) {
    const int nb = blockIdx.x;               // [0, S4_ROWS)
    const int c = threadIdx.x;
    const int n = nb - S4_PADL;
    float v = 0.f;
    if (n >= 0 && n < S4_N) {
        const int ci = __ldg(&sel[c]);
        const float* xp = x + (size_t)(4 * n) * C_IN + ci;
        v = (xp[0] + xp[C_IN]) + (xp[2 * C_IN] + xp[3 * C_IN]);
    }
    g_S4[(size_t)nb * 256 + c] = v;
}

// ------------------- K3b: mean(low) numerator -------------------
__global__ void k3b_mean(int K, int pad) {
    const int n = blockIdx.x * 256 + threadIdx.x;
    float part = 0.f;
    if (n < S4_N) {
        const float4* row = (const float4*)(g_S4 + (size_t)(n + S4_PADL) * 256);
        float s = 0.f;
        #pragma unroll 8
        for (int i = 0; i < 64; i++) { float4 v = row[i]; s += (v.x + v.y) + (v.z + v.w); }
        float cf = 0.f;
        #pragma unroll
        for (int i = 0; i < 4; i++) {
            int m = 4 * n + i;
            cf += g_P[min(m + pad + 1, K)] - g_P[max(0, m + pad + 1 - T_LEN)];
        }
        part = s * cf * 0.25f;
    }
    #pragma unroll
    for (int o = 16; o > 0; o >>= 1) part += __shfl_down_sync(0xffffffffu, part, o);
    __shared__ float sw[8];
    if ((threadIdx.x & 31) == 0) sw[threadIdx.x >> 5] = part;
    __syncthreads();
    if (threadIdx.x == 0) {
        float s = 0.f;
        #pragma unroll
        for (int i = 0; i < 8; i++) s += sw[i];
        atomicAdd(&g_mean_num, s);
    }
}

// ------------------- K4: low-pass node values (one phase per block) -------------------
// grid (98, 16): 2 node-groups per block, phase r = blockIdx.y.
__global__ void __launch_bounds__(256) k4_lownodes() {
    const int warp = threadIdx.x >> 5, lane = threadIdx.x & 31;
    const int grp = blockIdx.x * 2 + (warp >> 2);   // node group [0,196)
    const int cp  = (warp & 3) * 32 + lane;         // float2 channel index [0,128)
    const int r   = blockIdx.y;                     // phase [0,16)
    const int j0  = grp * 8;

    float2 acc[8];
    #pragma unroll
    for (int i = 0; i < 8; i++) acc[i] = make_float2(0.f, 0.f);

    const float2* S42 = (const float2*)g_S4;
    const int roff = r - 1500 + 16 * (j0 - 1) + S4_PADL;  // buffer row at v=0

    float wprev[7];
    #pragma unroll
    for (int t = 0; t < 7; t++) wprev[t] = 0.f;           // W(e<0) = 0 (padding)
    for (int vb = 0; vb < 200; vb += 8) {
        float w8[8];
        #pragma unroll
        for (int u = 0; u < 8; u++) w8[u] = g_WA[WA_PAD + 16 * (vb + u) + r];
        #pragma unroll
        for (int u = 0; u < 8; u++) {
            float2 sv = S42[(size_t)(16 * (vb + u) + roff) * 128 + cp];
            #pragma unroll
            for (int ii = 0; ii < 8; ii++) {
                int e = u - ii;
                float w = (e >= 0) ? w8[e] : wprev[7 + e];
                acc[ii].x += sv.x * w;
                acc[ii].y += sv.y * w;
            }
        }
        #pragma unroll
        for (int t = 0; t < 7; t++) wprev[t] = w8[t + 1];
    }
    float2* out = (float2*)(g_LNp + (size_t)r * NLN * 256);
    #pragma unroll
    for (int ii = 0; ii < 8; ii++)
        out[(size_t)(j0 + ii) * 128 + cp] = acc[ii];
}

// ------------------- K4c: combine 16 phase partials -------------------
__global__ void k4c_combine() {
    const size_t i = (size_t)blockIdx.x * 256 + threadIdx.x;   // NLN*256
    const size_t S = (size_t)NLN * 256;
    float s = 0.f;
    #pragma unroll
    for (int p = 0; p < NPHASE; p++) s += g_LNp[(size_t)p * S + i];
    g_LN[i] = s;
}

// ------------------- K5: materialize filt = x - interp(low) + mean (zero padded) -------------------
__global__ void k5_filt(const float* __restrict__ x, const int* __restrict__ sel) {
    const int row = blockIdx.x;            // [0, F_ROWS)
    const int m = row - F_PADL;
    const int c = threadIdx.x;
    float v = 0.f;
    if (m >= 0 && m < T_LEN) {
        const int j0 = m >> 6;
        const float s = (float)(m & 63) * (1.f / 64.f);
        const float sm1 = s + 1.f, s1 = s - 1.f, s2 = s - 2.f;
        const float wm1 = -s * s1 * s2 * (1.f / 6.f);
        const float w0  = sm1 * s1 * s2 * 0.5f;
        const float w1  = -sm1 * s * s2 * 0.5f;
        const float w2  = sm1 * s * s1 * (1.f / 6.f);
        const float* ln = g_LN + (size_t)j0 * 256 + c;
        const float lowI = wm1 * ln[0] + w0 * ln[256] + w1 * ln[512] + w2 * ln[768];
        const float mean = g_mean_num * (1.f / 25600000.f);
        v = x[(size_t)m * C_IN + __ldg(&sel[c])] - lowI + mean;
    }
    g_FILT[(size_t)row * 256 + c] = v;
}

// ------------------- K6: high-pass conv at stride-8 output nodes -------------------
// Node i at t = 8i - 8. Y[i] = sum_k wh[k] * filt[t + k - pad].
// Tap offsets restricted to ~±5 sigma (c' in [-62,65]). Phases rr split 2-way
// over grid.y into partial buffers.
__global__ void __launch_bounds__(256) k6_conv(const float* __restrict__ wh, int wc) {
    const int warp = threadIdx.x >> 5, lane = threadIdx.x & 31;
    const int grp = blockIdx.x * 2 + (warp >> 2);   // node group [0,1564)
    const int cp  = (warp & 3) * 32 + lane;         // float2 channel index [0,128)
    const int i0  = grp * 8;
    const int rbase = blockIdx.y * 4;               // phase half {0,4}

    float2 acc[8];
    #pragma unroll
    for (int i = 0; i < 8; i++) acc[i] = make_float2(0.f, 0.f);

    const float2* F2 = (const float2*)g_FILT;

    for (int rr2 = 0; rr2 < 4; rr2++) {
        const int rr = rbase + rr2;
        float wprev[7];
        #pragma unroll
        for (int t = 0; t < 7; t++) wprev[t] = __ldg(&wh[wc + 8 * (-63 + t) + rr]);
        for (int cb = -56; cb <= 56; cb += 8) {
            float w8[8];
            #pragma unroll
            for (int u = 0; u < 8; u++) w8[u] = __ldg(&wh[wc + 8 * (cb + u) + rr]);
            #pragma unroll
            for (int u = 0; u < 8; u++) {
                const int m = 8 * (i0 + cb + u) + rr;   // filt time index
                float2 fv = F2[(size_t)(m + F_PADL) * 128 + cp];
                #pragma unroll
                for (int ii = 0; ii < 8; ii++) {
                    int e = u - ii;
                    float w = (e >= 0) ? w8[e] : wprev[7 + e];
                    acc[ii].x += fv.x * w;
                    acc[ii].y += fv.y * w;
                }
            }
            #pragma unroll
            for (int t = 0; t < 7; t++) wprev[t] = w8[t + 1];
        }
    }
    float2* Y2 = (float2*)(g_YNp + (size_t)blockIdx.y * NYN * 256);
    #pragma unroll
    for (int ii = 0; ii < 8; ii++)
        Y2[(size_t)(i0 + ii) * 128 + cp] = acc[ii];
}

// ------------------- K7: combine Y partials + cubic interpolation to output -------------------
__global__ void k7_out(float* __restrict__ out) {
    const int t  = blockIdx.x * 4 + (threadIdx.x >> 6);
    const int cq = threadIdx.x & 63;
    const int i0 = t >> 3;
    const float s = (float)(t & 7) * 0.125f;
    const float sm1 = s + 1.f, s1 = s - 1.f, s2 = s - 2.f;
    const float wm1 = -s * s1 * s2 * (1.f / 6.f);
    const float w0  = sm1 * s1 * s2 * 0.5f;
    const float w1  = -sm1 * s * s2 * 0.5f;
    const float w2  = sm1 * s * s1 * (1.f / 6.f);
    const float4* Ya = (const float4*)g_YNp + (size_t)i0 * 64 + cq;
    const float4* Yb = Ya + (size_t)NYN * 64;
    float4 a0 = Ya[0],   b0 = Ya[64],  c0 = Ya[128], d0 = Ya[192];
    float4 a1 = Yb[0],   b1 = Yb[64],  c1 = Yb[128], d1 = Yb[192];
    float4 r;
    r.x = wm1 * (a0.x + a1.x) + w0 * (b0.x + b1.x) + w1 * (c0.x + c1.x) + w2 * (d0.x + d1.x);
    r.y = wm1 * (a0.y + a1.y) + w0 * (b0.y + b1.y) + w1 * (c0.y + c1.y) + w2 * (d0.y + d1.y);
    r.z = wm1 * (a0.z + a1.z) + w0 * (b0.z + b1.z) + w1 * (c0.z + c1.z) + w2 * (d0.z + d1.z);
    r.w = wm1 * (a0.w + a1.w) + w0 * (b0.w + b1.w) + w1 * (c0.w + c1.w) + w2 * (d0.w + d1.w);
    ((float4*)out)[(size_t)t * 64 + cq] = r;
}

// ------------------- launch -------------------
extern "C" void kernel_launch(void* const* d_in, const int* in_sizes, int n_in,
                              void* d_out, int out_size) {
    const float* x   = (const float*)d_in[0];   // firings (1,100000,512)
    const float* gl  = (const float*)d_in[1];   // gauss_low (K taps)
    const float* gh  = (const float*)d_in[2];   // gauss_high (K taps)
    const int*   sel = (const int*)d_in[3];     // sel_idx (256)
    float* out = (float*)d_out;

    const int K   = in_sizes[1];                // 12001 (arange fp quirk)
    const int pad = (K - 1) / 2;                // TF SAME left pad

    (void)n_in; (void)out_size;

    k2_prep<<<1, 256>>>(gl, K, pad);
    k3_presum<<<S4_ROWS, 256>>>(x, sel);
    k3b_mean<<<98, 256>>>(K, pad);
    k4_lownodes<<<dim3(98, NPHASE), 256>>>();
    k4c_combine<<<NLN, 256>>>();
    k5_filt<<<F_ROWS, 256>>>(x, sel);
    k6_conv<<<dim3(782, 2), 256>>>(gh, pad + 8);
    k7_out<<<25000, 256>>>(out);
}

// round 7
// speedup vs baseline: 1.6507x; 1.1512x over previous
#include <cuda_runtime.h>
#include <cuda_bf16.h>

// FrequencyFilter: gather 256 ch -> K-tap gauss_low (sigma=2000 samp) low-pass
// -> filt = x - low + mean(low) -> K-tap gauss_high (sigma=100 samp) smoothing.
// K = 12001, pad = (K-1)//2 = 6000 (parameterized at runtime).
//
// Strategy: both Gaussians are heavily bandlimited.
//  * low computed at stride-64 nodes from 4-sample presums (S4) with aggregated
//    4-tap weights (16-phase polyphase, phase-per-block), cubic interpolated.
//  * output computed at stride-8 nodes (8-phase polyphase over ~±5 sigma of
//    gauss_high, phases split over 2 blocks), cubic interpolated to full res.
//  * mean(low) via prefix sums of gauss_low + channel-summed S4.
//  * inner loops use Blackwell packed fma.rn.f32x2 (2 fp32 FMA / instr).

#define T_LEN   100000
#define C_SEL   256
#define C_IN    512

// ---- low-pass stage ----
#define S4_N     25000            // 4-sample presum blocks
#define S4_PADL  1520
#define S4_PADR  1664
#define S4_ROWS  (S4_PADL + S4_N + S4_PADR)   // 28184
#define WA_PAD   128
#define WA_SIZE  3456             // padded aggregated low kernel (3001 valid)
#define NLN      1568             // low nodes, node j at t = 64*(j-1)
#define NPHASE   16

// ---- filt buffer (zero padded in time) ----
#define F_PADL   640
#define F_PADR   736
#define F_ROWS   (F_PADL + T_LEN + F_PADR)    // 101376

// ---- high-pass output nodes ----
#define NYN      12512            // node i at t = 8*i - 8 (12503 used + slack)

typedef unsigned long long ull;

// ------------------- packed f32x2 helpers (sm_103a) -------------------
__device__ __forceinline__ ull pack2f(float v) {
    ull r; asm("mov.b64 %0, {%1, %1};" : "=l"(r) : "f"(v)); return r;
}
__device__ __forceinline__ void ffma2(ull& d, ull a, ull b) {
    asm("fma.rn.f32x2 %0, %1, %2, %0;" : "+l"(d) : "l"(a), "l"(b));
}

// ------------------- device scratch (static, no allocation) -------------------
__device__ __align__(16) float g_P[12002];                 // prefix of gauss_low
__device__ __align__(16) float g_WA[WA_SIZE];              // aggregated low kernel /4
__device__ float g_mean_num;                               // numerator of mean(low)
__device__ __align__(16) float g_S4[(size_t)S4_ROWS * 256];            // 28.9 MB
__device__ __align__(16) float g_LNp[(size_t)NPHASE * NLN * 256];      // 25.7 MB
__device__ __align__(16) float g_LN[NLN * 256];                        // 1.6 MB
__device__ __align__(16) float g_FILT[(size_t)F_ROWS * 256];           // 103.8 MB
__device__ __align__(16) float g_YNp[(size_t)2 * NYN * 256];           // 25.6 MB

// ------------------- K2: prefix of gauss_low + aggregated kernel + init -------------------
__global__ void k2_prep(const float* __restrict__ gl, int K, int pad) {
    __shared__ float tot[256];
    const int tid = threadIdx.x;
    const int base = tid * 48;
    float s = 0.f;
    for (int i = 0; i < 48; i++) { int k = base + i; if (k < K) s += gl[k]; }
    tot[tid] = s;
    __syncthreads();
    if (tid == 0) {
        float run = 0.f;
        for (int i = 0; i < 256; i++) { float v = tot[i]; tot[i] = run; run += v; }
        g_P[K] = run;
        g_mean_num = 0.f;
    }
    __syncthreads();
    float run = tot[tid];
    for (int i = 0; i < 48; i++) {
        int k = base + i;
        if (k < K) { g_P[k] = run; run += gl[k]; }
    }
    __syncthreads();
    // aggregated 4-tap low kernel (averaged weight); block QQ holds taps
    // k = 4*(QQ-1500) + pad + {0..3}, zero outside QQ in [0,3000]
    for (int q = tid; q < WA_SIZE; q += 256) {
        int QQ = q - WA_PAD;
        float v = 0.f;
        if (QQ >= 0 && QQ <= 3000) {
            int lo = 4 * QQ - 6000 + pad;
            int hi = min(lo + 4, K);
            lo = max(lo, 0);
            if (hi > lo) v = 0.25f * (g_P[hi] - g_P[lo]);
        }
        g_WA[q] = v;
    }
}

// ------------------- K3: 4-sample presums (zero-padded rows) -------------------
__global__ void k3_presum(const float* __restrict__ x, const int* __restrict__ sel) {
    const int nb = blockIdx.x;               // [0, S4_ROWS)
    const int c = threadIdx.x;
    const int n = nb - S4_PADL;
    float v = 0.f;
    if (n >= 0 && n < S4_N) {
        const int ci = __ldg(&sel[c]);
        const float* xp = x + (size_t)(4 * n) * C_IN + ci;
        v = (xp[0] + xp[C_IN]) + (xp[2 * C_IN] + xp[3 * C_IN]);
    }
    g_S4[(size_t)nb * 256 + c] = v;
}

// ------------------- K3b: mean(low) numerator -------------------
__global__ void k3b_mean(int K, int pad) {
    const int n = blockIdx.x * 256 + threadIdx.x;
    float part = 0.f;
    if (n < S4_N) {
        const float4* row = (const float4*)(g_S4 + (size_t)(n + S4_PADL) * 256);
        float s = 0.f;
        #pragma unroll 8
        for (int i = 0; i < 64; i++) { float4 v = row[i]; s += (v.x + v.y) + (v.z + v.w); }
        float cf = 0.f;
        #pragma unroll
        for (int i = 0; i < 4; i++) {
            int m = 4 * n + i;
            cf += g_P[min(m + pad + 1, K)] - g_P[max(0, m + pad + 1 - T_LEN)];
        }
        part = s * cf * 0.25f;
    }
    #pragma unroll
    for (int o = 16; o > 0; o >>= 1) part += __shfl_down_sync(0xffffffffu, part, o);
    __shared__ float sw[8];
    if ((threadIdx.x & 31) == 0) sw[threadIdx.x >> 5] = part;
    __syncthreads();
    if (threadIdx.x == 0) {
        float s = 0.f;
        #pragma unroll
        for (int i = 0; i < 8; i++) s += sw[i];
        atomicAdd(&g_mean_num, s);
    }
}

// ------------------- K4: low-pass node values (one phase per block, FFMA2) -------------------
// grid (98, 16): 2 node-groups per block, phase r = blockIdx.y.
__global__ void __launch_bounds__(256) k4_lownodes() {
    const int warp = threadIdx.x >> 5, lane = threadIdx.x & 31;
    const int grp = blockIdx.x * 2 + (warp >> 2);   // node group [0,196)
    const int cp  = (warp & 3) * 32 + lane;         // float2 channel index [0,128)
    const int r   = blockIdx.y;                     // phase [0,16)
    const int j0  = grp * 8;

    ull acc[8];
    #pragma unroll
    for (int i = 0; i < 8; i++) acc[i] = 0ULL;      // +0.0f in both lanes

    const ull* S4u = (const ull*)g_S4;
    const int roff = r - 1500 + 16 * (j0 - 1) + S4_PADL;  // buffer row at v=0

    ull wprev[7];
    #pragma unroll
    for (int t = 0; t < 7; t++) wprev[t] = 0ULL;          // W(e<0) = 0 (padding)
    for (int vb = 0; vb < 200; vb += 8) {
        ull w8[8];
        #pragma unroll
        for (int u = 0; u < 8; u++) w8[u] = pack2f(g_WA[WA_PAD + 16 * (vb + u) + r]);
        #pragma unroll
        for (int u = 0; u < 8; u++) {
            ull sv = S4u[(size_t)(16 * (vb + u) + roff) * 128 + cp];
            #pragma unroll
            for (int ii = 0; ii < 8; ii++) {
                int e = u - ii;
                ffma2(acc[ii], sv, (e >= 0) ? w8[e] : wprev[7 + e]);
            }
        }
        #pragma unroll
        for (int t = 0; t < 7; t++) wprev[t] = w8[t + 1];
    }
    ull* out = (ull*)(g_LNp + (size_t)r * NLN * 256);
    #pragma unroll
    for (int ii = 0; ii < 8; ii++)
        out[(size_t)(j0 + ii) * 128 + cp] = acc[ii];
}

// ------------------- K4c: combine 16 phase partials -------------------
__global__ void k4c_combine() {
    const size_t i = (size_t)blockIdx.x * 256 + threadIdx.x;   // NLN*256
    const size_t S = (size_t)NLN * 256;
    float s = 0.f;
    #pragma unroll
    for (int p = 0; p < NPHASE; p++) s += g_LNp[(size_t)p * S + i];
    g_LN[i] = s;
}

// ------------------- K5: materialize filt = x - interp(low) + mean (zero padded) -------------------
__global__ void k5_filt(const float* __restrict__ x, const int* __restrict__ sel) {
    const int row = blockIdx.x;            // [0, F_ROWS)
    const int m = row - F_PADL;
    const int c = threadIdx.x;
    float v = 0.f;
    if (m >= 0 && m < T_LEN) {
        const int j0 = m >> 6;
        const float s = (float)(m & 63) * (1.f / 64.f);
        const float sm1 = s + 1.f, s1 = s - 1.f, s2 = s - 2.f;
        const float wm1 = -s * s1 * s2 * (1.f / 6.f);
        const float w0  = sm1 * s1 * s2 * 0.5f;
        const float w1  = -sm1 * s * s2 * 0.5f;
        const float w2  = sm1 * s * s1 * (1.f / 6.f);
        const float* ln = g_LN + (size_t)j0 * 256 + c;
        const float lowI = wm1 * ln[0] + w0 * ln[256] + w1 * ln[512] + w2 * ln[768];
        const float mean = g_mean_num * (1.f / 25600000.f);
        v = x[(size_t)m * C_IN + __ldg(&sel[c])] - lowI + mean;
    }
    g_FILT[(size_t)row * 256 + c] = v;
}

// ------------------- K6: high-pass conv at stride-8 output nodes (FFMA2) -------------------
// Node i at t = 8i - 8. Y[i] = sum_k wh[k] * filt[t + k - pad].
// Tap offsets restricted to ~±5 sigma (c' in [-62,65]). Phases rr split 2-way
// over grid.y into partial buffers.
__global__ void __launch_bounds__(256) k6_conv(const float* __restrict__ wh, int wc) {
    const int warp = threadIdx.x >> 5, lane = threadIdx.x & 31;
    const int grp = blockIdx.x * 2 + (warp >> 2);   // node group [0,1564)
    const int cp  = (warp & 3) * 32 + lane;         // float2 channel index [0,128)
    const int i0  = grp * 8;
    const int rbase = blockIdx.y * 4;               // phase half {0,4}

    ull acc[8];
    #pragma unroll
    for (int i = 0; i < 8; i++) acc[i] = 0ULL;

    const ull* F2u = (const ull*)g_FILT;

    for (int rr2 = 0; rr2 < 4; rr2++) {
        const int rr = rbase + rr2;
        ull wprev[7];
        #pragma unroll
        for (int t = 0; t < 7; t++) wprev[t] = pack2f(__ldg(&wh[wc + 8 * (-63 + t) + rr]));
        for (int cb = -56; cb <= 56; cb += 8) {
            ull w8[8];
            #pragma unroll
            for (int u = 0; u < 8; u++) w8[u] = pack2f(__ldg(&wh[wc + 8 * (cb + u) + rr]));
            #pragma unroll
            for (int u = 0; u < 8; u++) {
                const int m = 8 * (i0 + cb + u) + rr;   // filt time index
                ull fv = F2u[(size_t)(m + F_PADL) * 128 + cp];
                #pragma unroll
                for (int ii = 0; ii < 8; ii++) {
                    int e = u - ii;
                    ffma2(acc[ii], fv, (e >= 0) ? w8[e] : wprev[7 + e]);
                }
            }
            #pragma unroll
            for (int t = 0; t < 7; t++) wprev[t] = w8[t + 1];
        }
    }
    ull* Y2 = (ull*)(g_YNp + (size_t)blockIdx.y * NYN * 256);
    #pragma unroll
    for (int ii = 0; ii < 8; ii++)
        Y2[(size_t)(i0 + ii) * 128 + cp] = acc[ii];
}

// ------------------- K7: combine Y partials + cubic interpolation to output -------------------
__global__ void k7_out(float* __restrict__ out) {
    const int t  = blockIdx.x * 4 + (threadIdx.x >> 6);
    const int cq = threadIdx.x & 63;
    const int i0 = t >> 3;
    const float s = (float)(t & 7) * 0.125f;
    const float sm1 = s + 1.f, s1 = s - 1.f, s2 = s - 2.f;
    const float wm1 = -s * s1 * s2 * (1.f / 6.f);
    const float w0  = sm1 * s1 * s2 * 0.5f;
    const float w1  = -sm1 * s * s2 * 0.5f;
    const float w2  = sm1 * s * s1 * (1.f / 6.f);
    const float4* Ya = (const float4*)g_YNp + (size_t)i0 * 64 + cq;
    const float4* Yb = Ya + (size_t)NYN * 64;
    float4 a0 = Ya[0],   b0 = Ya[64],  c0 = Ya[128], d0 = Ya[192];
    float4 a1 = Yb[0],   b1 = Yb[64],  c1 = Yb[128], d1 = Yb[192];
    float4 r;
    r.x = wm1 * (a0.x + a1.x) + w0 * (b0.x + b1.x) + w1 * (c0.x + c1.x) + w2 * (d0.x + d1.x);
    r.y = wm1 * (a0.y + a1.y) + w0 * (b0.y + b1.y) + w1 * (c0.y + c1.y) + w2 * (d0.y + d1.y);
    r.z = wm1 * (a0.z + a1.z) + w0 * (b0.z + b1.z) + w1 * (c0.z + c1.z) + w2 * (d0.z + d1.z);
    r.w = wm1 * (a0.w + a1.w) + w0 * (b0.w + b1.w) + w1 * (c0.w + c1.w) + w2 * (d0.w + d1.w);
    ((float4*)out)[(size_t)t * 64 + cq] = r;
}

// ------------------- launch -------------------
extern "C" void kernel_launch(void* const* d_in, const int* in_sizes, int n_in,
                              void* d_out, int out_size) {
    const float* x   = (const float*)d_in[0];   // firings (1,100000,512)
    const float* gl  = (const float*)d_in[1];   // gauss_low (K taps)
    const float* gh  = (const float*)d_in[2];   // gauss_high (K taps)
    const int*   sel = (const int*)d_in[3];     // sel_idx (256)
    float* out = (float*)d_out;

    const int K   = in_sizes[1];                // 12001 (arange fp quirk)
    const int pad = (K - 1) / 2;                // TF SAME left pad

    (void)n_in; (void)out_size;

    k2_prep<<<1, 256>>>(gl, K, pad);
    k3_presum<<<S4_ROWS, 256>>>(x, sel);
    k3b_mean<<<98, 256>>>(K, pad);
    k4_lownodes<<<dim3(98, NPHASE), 256>>>();
    k4c_combine<<<NLN, 256>>>();
    k5_filt<<<F_ROWS, 256>>>(x, sel);
    k6_conv<<<dim3(782, 2), 256>>>(gh, pad + 8);
    k7_out<<<25000, 256>>>(out);
}